// round 16
// baseline (speedup 1.0000x reference)
#include <cuda_runtime.h>
#include <cuda_fp16.h>

#define NB 8
#define NC 64
#define SH 128
#define SW 128
#define HW (SH*SW)
#define KT 21

typedef unsigned long long u64;
typedef unsigned int u32;

// ---------------- scratch (device globals; no allocations) ----------------
__device__ __align__(16) __half g_Whh[KT*4096];    // fp16 folded W [t][co][ci]
__device__ __align__(16) __half g_Wwh[KT*4096];
__device__ __align__(16) __half g_xt[(u64)NB*SH*SW*NC]; // NHWC fp16 input
__device__ __align__(16) float g_rbh[NC*SH];
__device__ __align__(16) float g_rbw[NC*SW];
__device__ __align__(16) __half g_hqh[(u64)NB*192*HW];  // h-branch qkv hi
__device__ __align__(16) __half g_hql[(u64)NB*192*HW];  // h-branch qkv lo
__device__ __align__(16) __half g_wqh[(u64)NB*192*HW];
__device__ __align__(16) __half g_wql[(u64)NB*192*HW];
__device__ __align__(16) __half g_Ph[2*64*SW*SW];       // P hi
__device__ __align__(16) __half g_Pl[2*64*SW*SW];       // P lo
__device__ __align__(16) float g_wo[NB*NC*HW];
__device__ __align__(16) float g_ho[NB*NC*HW];

// ---------------- fp16 mma / ldmatrix helpers -------------------------------
__device__ __forceinline__ void mma_f16(float* d, const u32* a, const u32* b){
    asm volatile("mma.sync.aligned.m16n8k16.row.col.f32.f16.f16.f32 "
        "{%0,%1,%2,%3}, {%4,%5,%6,%7}, {%8,%9}, {%0,%1,%2,%3};\n"
        : "+f"(d[0]), "+f"(d[1]), "+f"(d[2]), "+f"(d[3])
        : "r"(a[0]), "r"(a[1]), "r"(a[2]), "r"(a[3]), "r"(b[0]), "r"(b[1]));
}
__device__ __forceinline__ void ldsm_x4(u32& r0,u32& r1,u32& r2,u32& r3, u32 addr){
    asm volatile("ldmatrix.sync.aligned.m8n8.x4.shared.b16 {%0,%1,%2,%3}, [%4];"
        : "=r"(r0),"=r"(r1),"=r"(r2),"=r"(r3) : "r"(addr));
}
__device__ __forceinline__ void ldsm_x4t(u32& r0,u32& r1,u32& r2,u32& r3, u32 addr){
    asm volatile("ldmatrix.sync.aligned.m8n8.x4.trans.shared.b16 {%0,%1,%2,%3}, [%4];"
        : "=r"(r0),"=r"(r1),"=r"(r2),"=r"(r3) : "r"(addr));
}

// ---------------- cp.async helpers -----------------------------------------
__device__ __forceinline__ u32 smem_u32(const void* p){
    u32 a; asm("{ .reg .u64 t; cvta.to.shared.u64 t, %1; cvt.u32.u64 %0, t; }"
               : "=r"(a) : "l"(p));
    return a;
}
__device__ __forceinline__ void cpa16(u32 dst, const void* src, u32 srcsize){
    asm volatile("cp.async.cg.shared.global [%0], [%1], 16, %2;"
                 :: "r"(dst), "l"(src), "r"(srcsize) : "memory");
}
#define CPA_COMMIT() asm volatile("cp.async.commit_group;" ::: "memory")
#define CPA_WAIT0()  asm volatile("cp.async.wait_group 0;" ::: "memory")
#define CPA_WAIT1()  asm volatile("cp.async.wait_group 1;" ::: "memory")

// ---------------- f32x2 packed fma helpers (exact fp32 math) ---------------
__device__ __forceinline__ u64 pack2(float x, float y){
    u64 r; asm("mov.b64 %0, {%1,%2};" : "=l"(r) : "f"(x), "f"(y)); return r;
}
__device__ __forceinline__ void ffma2(u64& d, u64 a, u64 b){
    asm("fma.rn.f32x2 %0, %1, %2, %0;" : "+l"(d) : "l"(a), "l"(b));
}
__device__ __forceinline__ float2 unpack2(u64 d){
    float2 f; asm("mov.b64 {%0,%1}, %2;" : "=f"(f.x), "=f"(f.y) : "l"(d)); return f;
}

// split helpers: fp32 -> hi/lo fp16
__device__ __forceinline__ void split2(float x, float y, u32& hi, u32& lo){
    __half hx = __float2half_rn(x), hy = __float2half_rn(y);
    __half lx = __float2half_rn(x - __half2float(hx));
    __half ly = __float2half_rn(y - __half2float(hy));
    __half2 h = {hx, hy}, l = {lx, ly};
    hi = *(u32*)&h; lo = *(u32*)&l;
}

// ---------------- x -> NHWC fp16 transpose ---------------------------------
__global__ __launch_bounds__(256) void xt_kernel(const float* __restrict__ x)
{
    __shared__ __half T[NC*132];
    int h = blockIdx.x, b = blockIdx.y;
    int tid = threadIdx.x;
    #pragma unroll
    for (int i = 0; i < 8; i++){
        int idx4 = tid + i*256;
        int ci = idx4 >> 5, w4 = idx4 & 31;
        float4 v = *(const float4*)(x + (u64)(b*NC + ci)*HW + h*SW + w4*4);
        T[ci*132 + w4*4 + 0] = __float2half_rn(v.x);
        T[ci*132 + w4*4 + 1] = __float2half_rn(v.y);
        T[ci*132 + w4*4 + 2] = __float2half_rn(v.z);
        T[ci*132 + w4*4 + 3] = __float2half_rn(v.w);
    }
    __syncthreads();
    #pragma unroll
    for (int i = 0; i < 4; i++){
        int oct = tid + i*256;
        int w = oct >> 3, c8 = oct & 7;
        u32 rr[4];
        #pragma unroll
        for (int j = 0; j < 4; j++){
            __half2 hv;
            hv.x = T[(c8*8 + 2*j)*132 + w];
            hv.y = T[(c8*8 + 2*j + 1)*132 + w];
            rr[j] = *(u32*)&hv;
        }
        *(uint4*)(g_xt + ((u64)((b*SH + h)*SW + w))*NC + c8*8) =
            make_uint4(rr[0], rr[1], rr[2], rr[3]);
    }
}

// ---------------- prep: combine strip kernels, fold BN, fp16 W, biases -----
__global__ void prep_kernel(int side,
    const float* __restrict__ w7,  const float* __restrict__ b7,
    const float* __restrict__ w11, const float* __restrict__ b11,
    const float* __restrict__ w21, const float* __restrict__ b21,
    const float* __restrict__ bng, const float* __restrict__ bnb,
    const float* __restrict__ bnm, const float* __restrict__ bnv)
{
    __half* Wout = side ? g_Wwh : g_Whh;
    float* rbout = side ? g_rbw : g_rbh;
    int co = blockIdx.x;
    int tid = threadIdx.x;
    __shared__ float Wraw[NC*KT];
    __shared__ float Pfx[NC*(KT+1)];

    for (int idx = tid; idx < NC*KT; idx += blockDim.x){
        int ci = idx / KT, t = idx % KT;
        float v = w21[(co*NC+ci)*21 + t];
        if (t >= 5 && t < 16) v += w11[(co*NC+ci)*11 + (t-5)];
        if (t >= 7 && t < 14) v += w7 [(co*NC+ci)*7  + (t-7)];
        Wraw[idx] = v;
        float a = bng[ci] * rsqrtf(bnv[ci] + 1e-5f);
        Wout[t*4096 + co*64 + ci] = __float2half_rn(v * a);
    }
    __syncthreads();
    if (tid < NC){
        int ci = tid;
        float a = bng[ci] * rsqrtf(bnv[ci] + 1e-5f);
        float c = bnb[ci] - bnm[ci] * a;
        float s = 0.f;
        Pfx[ci*(KT+1)] = 0.f;
        for (int t = 0; t < KT; t++){
            s += Wraw[ci*KT + t] * c;
            Pfx[ci*(KT+1) + t + 1] = s;
        }
    }
    __syncthreads();
    float cb = b7[co] + b11[co] + b21[co];
    for (int h = tid; h < SH; h += blockDim.x){
        int t0 = 10 - h;  if (t0 < 0) t0 = 0;
        int t1 = 137 - h; if (t1 > KT-1) t1 = KT-1;
        float s = cb;
        for (int ci = 0; ci < NC; ci++)
            s += Pfx[ci*(KT+1) + t1 + 1] - Pfx[ci*(KT+1) + t0];
        rbout[co*SH + h] = s;
    }
}

// ======== fused conv (fp16 mma, ldmatrix) + qkv projection (split-fp16) =====
#define SROW 72
#define WSLAB (64*SROW)
#define DP_STR 264
#define WP_STR 72

__global__ __launch_bounds__(256, 2) void conv_fused_kernel(
    const float* __restrict__ hqkv_w, const float* __restrict__ hqkv_b,
    const float* __restrict__ wqkv_w, const float* __restrict__ wqkv_b)
{
    extern __shared__ char smem_raw[];
    __half* Xs = (__half*)smem_raw;            // 384 rows x 72 halves
    __half* Ws = Xs + 384*SROW;                // 2 W slabs
    int h0 = blockIdx.x * 2, b = blockIdx.y;
    int side = blockIdx.z;
    int tid = threadIdx.x;
    int wid = tid >> 5, lid = tid & 31;
    int gid = lid >> 2, tig = lid & 3;
    int r = wid >> 2, pxq = (wid & 3) * 32;
    u32 xs_b = smem_u32(Xs);
    u32 ws_b = smem_u32(Ws);
    // ldmatrix lane maps
    int mrA = (lid & 7) + ((lid >> 3) & 1) * 8;    // A: row offset within 16
    int ksA = (lid >> 4) * 8;                      // A: k col seg
    int nrB = (lid & 7) + (lid >> 4) * 8;          // B: n row offset within 16
    int kcB = ((lid >> 3) & 1) * 8;                // B: k col seg

    const __half* Wsrc = side ? g_Wwh : g_Whh;
    if (side){
        for (int i = tid; i < 296*8; i += 256){
            int row = i >> 3, c16 = i & 7;
            int rr = (row >= 148), wp = row - rr*148 - 10;
            uint4 v = make_uint4(0,0,0,0);
            if ((unsigned)wp < 128u)
                v = *(const uint4*)(g_xt + ((u64)((b*SH + h0 + rr)*SW + wp))*NC + c16*8);
            *(uint4*)(Xs + row*SROW + c16*8) = v;
        }
    } else {
        #pragma unroll
        for (int s = 0; s < 2; s++){
            int hp = h0 - 10 + s;
            int slot = (hp + 12) % 3;
            for (int i = tid; i < 128*8; i += 256){
                int w = i >> 3, c16 = i & 7;
                uint4 v = make_uint4(0,0,0,0);
                if ((unsigned)hp < 128u)
                    v = *(const uint4*)(g_xt + ((u64)((b*SH + hp)*SW + w))*NC + c16*8);
                *(uint4*)(Xs + (slot*128 + w)*SROW + c16*8) = v;
            }
        }
    }
    for (int i = tid; i < 512; i += 256){
        int row = i >> 3, c16 = i & 7;
        *(uint4*)(Ws + row*SROW + c16*8) = *(const uint4*)(Wsrc + row*64 + c16*8);
    }
    __syncthreads();

    float d[4][4][4];
    #pragma unroll
    for (int i = 0; i < 4; i++)
        #pragma unroll
        for (int j = 0; j < 4; j++)
            #pragma unroll
            for (int k = 0; k < 4; k++) d[i][j][k] = 0.f;

    #pragma unroll 1
    for (int t = 0; t < KT; t++){
        if (t < KT-1){
            if (!side){
                int nrow = h0 + t - 8;
                int slot = (nrow + 12) % 3;
                u32 ok = ((unsigned)nrow < 128u) ? 16u : 0u;
                int crow = nrow < 0 ? 0 : (nrow > 127 ? 127 : nrow);
                const __half* src = g_xt + ((u64)((b*SH + crow)*SW))*NC;
                #pragma unroll
                for (int i = 0; i < 4; i++){
                    int idx = tid + i*256;
                    int w = idx >> 3, c16 = idx & 7;
                    cpa16(xs_b + ((slot*128 + w)*SROW + c16*8)*2,
                          src + (u64)w*NC + c16*8, ok);
                }
            }
            {
                const __half* wsrc = Wsrc + (t+1)*4096;
                u32 wdst = ws_b + (((t+1) & 1)*WSLAB)*2;
                #pragma unroll
                for (int i = 0; i < 2; i++){
                    int idx = tid + i*256;
                    int row = idx >> 3, c16 = idx & 7;
                    cpa16(wdst + (row*SROW + c16*8)*2, wsrc + row*64 + c16*8, 16);
                }
            }
            CPA_COMMIT();
        }
        // ---- compute tap t via ldmatrix fragments ----
        u32 wtb = ws_b + ((t & 1)*WSLAB)*2;
        u32 xbb = side
            ? xs_b + ((u32)(r*148 + pxq + t)*SROW)*2
            : xs_b + ((u32)(((h0 + t + r + 2) % 3)*128 + pxq)*SROW)*2;
        #pragma unroll
        for (int kc = 0; kc < 4; kc++){
            u32 af[4][4];
            #pragma unroll
            for (int i = 0; i < 4; i++)
                ldsm_x4(af[i][0],af[i][1],af[i][2],af[i][3],
                        wtb + ((u32)(i*16 + mrA)*SROW + kc*16 + ksA)*2);
            u32 bf[4][2];
            #pragma unroll
            for (int jp = 0; jp < 2; jp++){
                u32 r0,r1,r2,r3;
                ldsm_x4(r0,r1,r2,r3,
                        xbb + ((u32)(jp*16 + nrB)*SROW + kc*16 + kcB)*2);
                bf[jp*2][0]=r0; bf[jp*2][1]=r1;
                bf[jp*2+1][0]=r2; bf[jp*2+1][1]=r3;
            }
            #pragma unroll
            for (int i = 0; i < 4; i++)
                #pragma unroll
                for (int j = 0; j < 4; j++)
                    mma_f16(d[i][j], af[i], bf[j]);
        }
        if (t < KT-1){
            CPA_WAIT0();
            __syncthreads();
        }
    }

    // ====== Phase 2: qkv projection via split-fp16 mma ======================
    __half* Dh  = (__half*)smem_raw;           // [64 ci][264]
    __half* Dl  = Dh + 64*DP_STR;
    __half* W2h = Dl + 64*DP_STR;              // [64 o][72]
    __half* W2l = W2h + 64*WP_STR;
    const float* w2   = side ? wqkv_w : hqkv_w;
    const float* bias = side ? wqkv_b : hqkv_b;
    __half* qh = side ? g_wqh : g_hqh;
    __half* ql = side ? g_wql : g_hql;

    __syncthreads();   // conv smem reads done
    #pragma unroll
    for (int i = 0; i < 4; i++){
        #pragma unroll
        for (int half = 0; half < 2; half++){
            int co = i*16 + gid + half*8;
            float rbv = side ? 0.f : g_rbh[co*SH + h0 + r];
            #pragma unroll
            for (int j = 0; j < 4; j++){
                int px256 = r*128 + pxq + j*8 + tig*2;
                float vx = d[i][j][half*2 + 0];
                float vy = d[i][j][half*2 + 1];
                if (side){
                    float2 bb = *(const float2*)(g_rbw + co*SW + ((pxq + j*8 + tig*2)));
                    vx += bb.x; vy += bb.y;
                } else { vx += rbv; vy += rbv; }
                u32 hi, lo;
                split2(vx, vy, hi, lo);
                *(u32*)&Dh[co*DP_STR + px256] = hi;
                *(u32*)&Dl[co*DP_STR + px256] = lo;
            }
        }
    }
    __syncthreads();

    int mw = wid & 1, nw = wid >> 1;
    int krB2 = (lid & 7) + ((lid >> 3) & 1) * 8;
    int ncB2 = (lid >> 4) * 8;
    u32 dh_b = smem_u32(Dh), dl_b = smem_u32(Dl);
    u32 w2h_b = smem_u32(W2h), w2l_b = smem_u32(W2l);

    #pragma unroll 1
    for (int og = 0; og < 3; og++){
        if (og) __syncthreads();
        for (int it = tid; it < 4096; it += 256){
            int o = it >> 6, ci = it & 63;
            float w = w2[og*4096 + it];
            __half hh = __float2half_rn(w);
            W2h[o*WP_STR + ci] = hh;
            W2l[o*WP_STR + ci] = __float2half_rn(w - __half2float(hh));
        }
        __syncthreads();
        float dd[2][8][4];
        #pragma unroll
        for (int i = 0; i < 2; i++)
            #pragma unroll
            for (int j = 0; j < 8; j++)
                #pragma unroll
                for (int k = 0; k < 4; k++) dd[i][j][k] = 0.f;
        #pragma unroll
        for (int kc = 0; kc < 4; kc++){
            u32 ah[2][4], al2[2][4];
            #pragma unroll
            for (int i = 0; i < 2; i++){
                int mb = mw*32 + i*16;
                ldsm_x4(ah[i][0],ah[i][1],ah[i][2],ah[i][3],
                        w2h_b + ((mb + mrA)*WP_STR + kc*16 + ksA)*2);
                ldsm_x4(al2[i][0],al2[i][1],al2[i][2],al2[i][3],
                        w2l_b + ((mb + mrA)*WP_STR + kc*16 + ksA)*2);
            }
            #pragma unroll
            for (int jp = 0; jp < 4; jp++){
                int jb = nw*64 + jp*16;
                u32 h0r,h1r,h2r,h3r, l0r,l1r,l2r,l3r;
                ldsm_x4t(h0r,h1r,h2r,h3r, dh_b + ((kc*16 + krB2)*DP_STR + jb + ncB2)*2);
                ldsm_x4t(l0r,l1r,l2r,l3r, dl_b + ((kc*16 + krB2)*DP_STR + jb + ncB2)*2);
                u32 BH[2][2] = {{h0r,h1r},{h2r,h3r}};
                u32 BL[2][2] = {{l0r,l1r},{l2r,l3r}};
                #pragma unroll
                for (int jj = 0; jj < 2; jj++){
                    int j = jp*2 + jj;
                    #pragma unroll
                    for (int i = 0; i < 2; i++){
                        mma_f16(dd[i][j], ah[i], BH[jj]);
                        mma_f16(dd[i][j], ah[i], BL[jj]);
                        mma_f16(dd[i][j], al2[i], BH[jj]);
                    }
                }
            }
        }
        #pragma unroll
        for (int i = 0; i < 2; i++){
            #pragma unroll
            for (int hf = 0; hf < 2; hf++){
                int o = og*64 + mw*32 + i*16 + gid + hf*8;
                float bv = bias[o];
                u64 obase = (u64)(b*192 + o)*HW;
                #pragma unroll
                for (int j = 0; j < 8; j++){
                    int px256 = nw*64 + j*8 + tig*2;
                    int r2 = px256 >> 7, px = px256 & 127;
                    float vx = dd[i][j][hf*2 + 0] + bv;
                    float vy = dd[i][j][hf*2 + 1] + bv;
                    u32 hi, lo;
                    split2(vx, vy, hi, lo);
                    u64 off = obase + (u64)(h0 + r2)*SW + px;
                    *(u32*)(qh + off) = hi;
                    *(u32*)(ql + off) = lo;
                }
            }
        }
    }
}

// ---------------- gemm_p: split-fp16 tensor, K=1024, direct Ph/Pl ----------
#define GP_MAT 2176
#define GP_BUF (4*GP_MAT)
__global__ __launch_bounds__(256, 2) void gemm_p_kernel()
{
    extern __shared__ __half PS[];
    int pair = blockIdx.x, which = blockIdx.y;
    int b = pair >> 3, nh = pair & 7;
    const __half* qh = which ? g_wqh : g_hqh;
    const __half* ql = which ? g_wql : g_hql;
    const __half* vh = which ? g_hqh : g_wqh;
    const __half* vl = which ? g_hql : g_wql;
    u64 aoff = (u64)(b*192 + nh*24 + 0 )*HW;
    u64 boff = (u64)(b*192 + nh*24 + 16)*HW;
    int tid = threadIdx.x, lid = tid & 31, wid = tid >> 5;
    int mw = wid >> 1, nw = wid & 1;
    int gid = lid >> 2, tig = lid & 3;

    float d[2][8][4];
    #pragma unroll
    for (int i = 0; i < 2; i++)
        #pragma unroll
        for (int j = 0; j < 8; j++)
            #pragma unroll
            for (int k = 0; k < 4; k++) d[i][j][k] = 0.f;

    int krA = (lid & 7) + ((lid >> 4) << 3);
    int mcA = ((lid >> 3) & 1) * 8;
    int krB = (lid & 7) + ((lid >> 3) & 1) * 8;
    int ncB = (lid >> 4) * 8;

    #pragma unroll 1
    for (int c = 0; c < 66; c++){
        if (c >= 2){
            if (c <= 64) CPA_WAIT1(); else CPA_WAIT0();
            __syncthreads();
        }
        if (c < 64){
            __half* B0 = PS + (c % 3)*GP_BUF;
            int k0 = c*16;
            #pragma unroll
            for (int i = 0; i < 4; i++){
                int id = tid + i*256;
                int mat = id >> 8, rem = id & 255;
                int kk = rem >> 4, seg = rem & 15;
                const __half* src =
                    (mat == 0 ? qh + aoff : mat == 1 ? ql + aoff :
                     mat == 2 ? vh + boff : vl + boff)
                    + (u64)(k0 + kk)*SW + seg*8;
                cpa16(smem_u32(B0 + mat*GP_MAT + kk*136 + seg*8), src, 16);
            }
            CPA_COMMIT();
        }
        if (c < 2) continue;
        int cc = c - 2;
        u32 base = smem_u32(PS + (cc % 3)*GP_BUF);
        u32 ah[2][4], al[2][4];
        #pragma unroll
        for (int i = 0; i < 2; i++){
            int mb = mw*32 + i*16;
            ldsm_x4t(ah[i][0],ah[i][1],ah[i][2],ah[i][3],
                     base + (0*GP_MAT + krA*136 + mb + mcA)*2);
            ldsm_x4t(al[i][0],al[i][1],al[i][2],al[i][3],
                     base + (1*GP_MAT + krA*136 + mb + mcA)*2);
        }
        #pragma unroll
        for (int jp = 0; jp < 4; jp++){
            int jb = nw*64 + jp*16;
            u32 h0,h1,h2,h3, l0,l1,l2,l3;
            ldsm_x4t(h0,h1,h2,h3, base + (2*GP_MAT + krB*136 + jb + ncB)*2);
            ldsm_x4t(l0,l1,l2,l3, base + (3*GP_MAT + krB*136 + jb + ncB)*2);
            u32 BH[2][2] = {{h0,h1},{h2,h3}};
            u32 BL[2][2] = {{l0,l1},{l2,l3}};
            #pragma unroll
            for (int jj = 0; jj < 2; jj++){
                int j = jp*2 + jj;
                #pragma unroll
                for (int i = 0; i < 2; i++){
                    mma_f16(d[i][j], ah[i], BH[jj]);
                    mma_f16(d[i][j], ah[i], BL[jj]);
                    mma_f16(d[i][j], al[i], BH[jj]);
                }
            }
        }
    }
    u64 pbase = (u64)(which*64 + pair)*16384;
    #pragma unroll
    for (int i = 0; i < 2; i++)
        #pragma unroll
        for (int j = 0; j < 8; j++)
            #pragma unroll
            for (int hf = 0; hf < 2; hf++){
                int m = mw*32 + i*16 + gid + hf*8;
                int n = nw*64 + j*8 + tig*2;
                u32 hi, lo;
                split2(d[i][j][hf*2], d[i][j][hf*2+1], hi, lo);
                *(u32*)(g_Ph + pbase + m*128 + n) = hi;
                *(u32*)(g_Pl + pbase + m*128 + n) = lo;
            }
}

// ---------------- gemm_o: split-fp16 tensor ---------------------------------
#define GO_A 3072
#define GO_B 2176
#define GO_BUF (2*GO_A + 2*GO_B)
__global__ __launch_bounds__(256, 2) void gemm_o_kernel()
{
    extern __shared__ __half OS[];
    int jt = blockIdx.x, pair = blockIdx.y, which = blockIdx.z;
    int b = pair >> 3, nh = pair & 7;
    const __half* kh = (which ? g_hqh : g_wqh) + (u64)(b*192 + nh*24 + 8 + jt)*HW;
    const __half* kl = (which ? g_hql : g_wql) + (u64)(b*192 + nh*24 + 8 + jt)*HW;
    const __half* ph = g_Ph + (u64)(which*64 + pair)*16384;
    const __half* pl = g_Pl + (u64)(which*64 + pair)*16384;
    float* out = which ? g_ho : g_wo;
    int tid = threadIdx.x, lid = tid & 31, wid = tid >> 5;
    int mw = wid >> 1, nw = wid & 1;
    int gid = lid >> 2, tig = lid & 3;

    float d[2][8][4];
    #pragma unroll
    for (int i = 0; i < 2; i++)
        #pragma unroll
        for (int j = 0; j < 8; j++)
            #pragma unroll
            for (int k = 0; k < 4; k++) d[i][j][k] = 0.f;

    int mrA = (lid & 7) + ((lid >> 3) & 1) * 8;
    int ksA = (lid >> 4) * 8;
    int krB = (lid & 7) + ((lid >> 3) & 1) * 8;
    int ncB = (lid >> 4) * 8;

    #pragma unroll 1
    for (int c = 0; c < 10; c++){
        if (c >= 2){
            if (c <= 8) CPA_WAIT1(); else CPA_WAIT0();
            __syncthreads();
        }
        if (c < 8){
            __half* B0 = OS + (c % 3)*GO_BUF;
            int t0 = c*16;
            #pragma unroll
            for (int i = 0; i < 4; i++){
                int id = tid + i*256;
                if (id < 512){
                    int mat = id >> 8, rem = id & 255;
                    int m = rem >> 1, seg = rem & 1;
                    const __half* src = (mat ? kl : kh) + m*128 + t0 + seg*8;
                    cpa16(smem_u32(B0 + mat*GO_A + m*24 + seg*8), src, 16);
                } else {
                    int id2 = id - 512;
                    int mat = id2 >> 8, rem = id2 & 255;
                    int kk = rem >> 4, seg = rem & 15;
                    const __half* src = (mat ? pl : ph) + (t0 + kk)*128 + seg*8;
                    cpa16(smem_u32(B0 + 2*GO_A + mat*GO_B + kk*136 + seg*8), src, 16);
                }
            }
            CPA_COMMIT();
        }
        if (c < 2) continue;
        int cc = c - 2;
        u32 base = smem_u32(OS + (cc % 3)*GO_BUF);
        u32 ah[2][4], al[2][4];
        #pragma unroll
        for (int i = 0; i < 2; i++){
            int mb = mw*32 + i*16;
            ldsm_x4(ah[i][0],ah[i][1],ah[i][2],ah[i][3],
                    base + (0*GO_A + (mb + mrA)*24 + ksA)*2);
            ldsm_x4(al[i][0],al[i][1],al[i][2],al[i][3],
                    base + (1*GO_A + (mb + mrA)*24 + ksA)*2);
        }
        #pragma unroll
        for (int jp = 0; jp < 4; jp++){
            int jb = nw*64 + jp*16;
            u32 h0,h1,h2,h3, l0,l1,l2,l3;
            ldsm_x4t(h0,h1,h2,h3, base + (2*GO_A + 0*GO_B + krB*136 + jb + ncB)*2);
            ldsm_x4t(l0,l1,l2,l3, base + (2*GO_A + 1*GO_B + krB*136 + jb + ncB)*2);
            u32 BH[2][2] = {{h0,h1},{h2,h3}};
            u32 BL[2][2] = {{l0,l1},{l2,l3}};
            #pragma unroll
            for (int jj = 0; jj < 2; jj++){
                int j = jp*2 + jj;
                #pragma unroll
                for (int i = 0; i < 2; i++){
                    mma_f16(d[i][j], ah[i], BH[jj]);
                    mma_f16(d[i][j], ah[i], BL[jj]);
                    mma_f16(d[i][j], al[i], BH[jj]);
                }
            }
        }
    }
    const float scale = 0.707106781186547524f;
    float* ob = out + (u64)(b*NC + nh*8 + jt)*HW;
    #pragma unroll
    for (int i = 0; i < 2; i++)
        #pragma unroll
        for (int j = 0; j < 8; j++)
            #pragma unroll
            for (int hf = 0; hf < 2; hf++){
                int m = mw*32 + i*16 + gid + hf*8;
                int n = nw*64 + j*8 + tig*2;
                *(float2*)&ob[m*SW + n] =
                    make_float2(d[i][j][hf*2]*scale, d[i][j][hf*2+1]*scale);
            }
}

// ---------------- epilogue: out-projections + sigmoid gate (f32x2) ---------
__global__ __launch_bounds__(128) void epi_kernel(const float* __restrict__ x,
    const float* __restrict__ wow, const float* __restrict__ wob,
    const float* __restrict__ how, const float* __restrict__ hob,
    float* __restrict__ out)
{
    extern __shared__ float sm[];
    float* Ws = sm;
    float* Hs = sm + 4352;
    float* Xw = sm + 8704;
    float* Xh = sm + 8704 + 2048;
    int pt = blockIdx.x, b = blockIdx.y;
    int px0 = pt * 128;
    int tid = threadIdx.x, ty = tid >> 4, tx = tid & 15;

    #pragma unroll
    for (int i = 0; i < 32; i++){
        int idx = tid + i*128;
        int o = idx >> 6, ci = idx & 63;
        Ws[ci*68 + o] = wow[idx];
        Hs[ci*68 + o] = how[idx];
    }
    u64 acc2[8][4];
    #pragma unroll
    for (int r = 0; r < 8; r++)
        #pragma unroll
        for (int j = 0; j < 4; j++) acc2[r][j] = 0ull;

    #pragma unroll 1
    for (int kc = 0; kc < 4; kc++){
        if (kc) __syncthreads();
        #pragma unroll
        for (int i = 0; i < 4; i++){
            int idx4 = tid + i*128;
            int ci = idx4 >> 5, p4 = idx4 & 31;
            ((float4*)Xw)[idx4] = *(const float4*)(g_wo + (u64)(b*NC + kc*16 + ci)*HW + px0 + p4*4);
            ((float4*)Xh)[idx4] = *(const float4*)(g_ho + (u64)(b*NC + kc*16 + ci)*HW + px0 + p4*4);
        }
        __syncthreads();
        const float4* Xwq = (const float4*)Xw;
        const float4* Xhq = (const float4*)Xh;
        #pragma unroll 2
        for (int c16 = 0; c16 < 16; c16++){
            int ci = kc*16 + c16;
            float4 aw0 = *(const float4*)(Ws + ci*68 + ty*8);
            float4 aw1 = *(const float4*)(Ws + ci*68 + ty*8 + 4);
            float4 ah0 = *(const float4*)(Hs + ci*68 + ty*8);
            float4 ah1 = *(const float4*)(Hs + ci*68 + ty*8 + 4);
            float4 xw0 = Xwq[c16*32 + tx];
            float4 xw1 = Xwq[c16*32 + tx + 16];
            float4 xh0 = Xhq[c16*32 + tx];
            float4 xh1 = Xhq[c16*32 + tx + 16];
            u64 dw[8] = {pack2(aw0.x,aw0.x), pack2(aw0.y,aw0.y), pack2(aw0.z,aw0.z), pack2(aw0.w,aw0.w),
                         pack2(aw1.x,aw1.x), pack2(aw1.y,aw1.y), pack2(aw1.z,aw1.z), pack2(aw1.w,aw1.w)};
            u64 dh[8] = {pack2(ah0.x,ah0.x), pack2(ah0.y,ah0.y), pack2(ah0.z,ah0.z), pack2(ah0.w,ah0.w),
                         pack2(ah1.x,ah1.x), pack2(ah1.y,ah1.y), pack2(ah1.z,ah1.z), pack2(ah1.w,ah1.w)};
            u64 xwd[4] = {pack2(xw0.x,xw0.y), pack2(xw0.z,xw0.w), pack2(xw1.x,xw1.y), pack2(xw1.z,xw1.w)};
            u64 xhd[4] = {pack2(xh0.x,xh0.y), pack2(xh0.z,xh0.w), pack2(xh1.x,xh1.y), pack2(xh1.z,xh1.w)};
            #pragma unroll
            for (int r = 0; r < 8; r++)
                #pragma unroll
                for (int j = 0; j < 4; j++){
                    ffma2(acc2[r][j], dw[r], xwd[j]);
                    ffma2(acc2[r][j], dh[r], xhd[j]);
                }
        }
    }
    #pragma unroll
    for (int r = 0; r < 8; r++){
        int c = ty*8 + r;
        float bv = wob[c] + hob[c];
        const float* xb = x + (u64)(b*NC + c)*HW + px0;
        float* ob = out + (u64)(b*NC + c)*HW + px0;
        float av[8];
        float2 p0 = unpack2(acc2[r][0]), p1 = unpack2(acc2[r][1]);
        float2 p2 = unpack2(acc2[r][2]), p3 = unpack2(acc2[r][3]);
        av[0]=p0.x; av[1]=p0.y; av[2]=p1.x; av[3]=p1.y;
        av[4]=p2.x; av[5]=p2.y; av[6]=p3.x; av[7]=p3.y;
        #pragma unroll
        for (int half = 0; half < 2; half++){
            float4 xv = *(const float4*)(xb + tx*4 + half*64);
            float vs[4];
            #pragma unroll
            for (int j = 0; j < 4; j++){
                float s = av[half*4 + j] + bv;
                vs[j] = (&xv.x)[j] * (1.f / (1.f + expf(-s)));
            }
            float4 v = {vs[0], vs[1], vs[2], vs[3]};
            *(float4*)(ob + tx*4 + half*64) = v;
        }
    }
}

// ---------------- launch ---------------------------------------------------
extern "C" void kernel_launch(void* const* d_in, const int* in_sizes, int n_in,
                              void* d_out, int out_size)
{
    const float* x = (const float*)d_in[0];
    int i1w[3], i1b[3], i2w[3], i2b[3];
    if (in_sizes[11] == 45056){ // reference-signature order
        i1w[0]=9;  i1w[1]=11; i1w[2]=13;  i1b[0]=10; i1b[1]=12; i1b[2]=14;
        i2w[0]=15; i2w[1]=17; i2w[2]=19;  i2b[0]=16; i2b[1]=18; i2b[2]=20;
    } else {                    // setup_inputs dict order
        i1w[0]=9;  i1w[1]=13; i1w[2]=17;  i1b[0]=10; i1b[1]=14; i1b[2]=18;
        i2w[0]=11; i2w[1]=15; i2w[2]=19;  i2b[0]=12; i2b[1]=16; i2b[2]=20;
    }
    const float* bn1g=(const float*)d_in[1]; const float* bn1b=(const float*)d_in[2];
    const float* bn1m=(const float*)d_in[3]; const float* bn1v=(const float*)d_in[4];
    const float* bn2g=(const float*)d_in[5]; const float* bn2b=(const float*)d_in[6];
    const float* bn2m=(const float*)d_in[7]; const float* bn2v=(const float*)d_in[8];
    const float* hqkvw=(const float*)d_in[21]; const float* hqkvb=(const float*)d_in[22];
    const float* wqkvw=(const float*)d_in[23]; const float* wqkvb=(const float*)d_in[24];
    const float* houtw=(const float*)d_in[25]; const float* houtb=(const float*)d_in[26];
    const float* woutw=(const float*)d_in[27]; const float* woutb=(const float*)d_in[28];

    int sm_conv = (2*64*DP_STR + 2*64*WP_STR) * 2;   // 86016 B (covers phase1's 73728)
    int sm_gp = 3*GP_BUF*2;                    // 52224 B
    int sm_go = 3*GO_BUF*2;                    // 62976 B
    cudaFuncSetAttribute(conv_fused_kernel, cudaFuncAttributeMaxDynamicSharedMemorySize, sm_conv);
    cudaFuncSetAttribute(gemm_p_kernel, cudaFuncAttributeMaxDynamicSharedMemorySize, sm_gp);
    cudaFuncSetAttribute(gemm_o_kernel, cudaFuncAttributeMaxDynamicSharedMemorySize, sm_go);
    cudaFuncSetAttribute(epi_kernel, cudaFuncAttributeMaxDynamicSharedMemorySize, 64*1024);

    xt_kernel<<<dim3(SH, NB), 256>>>(x);
    prep_kernel<<<NC, 128>>>(0,
        (const float*)d_in[i1w[0]], (const float*)d_in[i1b[0]],
        (const float*)d_in[i1w[1]], (const float*)d_in[i1b[1]],
        (const float*)d_in[i1w[2]], (const float*)d_in[i1b[2]],
        bn1g, bn1b, bn1m, bn1v);
    prep_kernel<<<NC, 128>>>(1,
        (const float*)d_in[i2w[0]], (const float*)d_in[i2b[0]],
        (const float*)d_in[i2w[1]], (const float*)d_in[i2b[1]],
        (const float*)d_in[i2w[2]], (const float*)d_in[i2b[2]],
        bn2g, bn2b, bn2m, bn2v);

    conv_fused_kernel<<<dim3(64, NB, 2), 256, sm_conv>>>(hqkvw, hqkvb, wqkvw, wqkvb);

    gemm_p_kernel<<<dim3(64, 2), 256, sm_gp>>>();
    gemm_o_kernel<<<dim3(8, 64, 2), 256, sm_go>>>();

    epi_kernel<<<dim3(128, NB), 128, (8704 + 4096)*4>>>(x, woutw, woutb, houtw, houtb,
                                                        (float*)d_out);
}